// round 1
// baseline (speedup 1.0000x reference)
#include <cuda_runtime.h>
#include <math.h>

#define HID   2048
#define NTOK  8192
#define NH    32
#define HD    64
#define BLK   256
#define NB    32            /* 8192 / 256 */
#define QKVW  (3*HID)       /* 6144 */

/* ------------------------- scratch (device globals) ------------------------ */
__device__ float g_qkv[(size_t)NTOK * QKVW];          /* 201 MB  silu(qkv)     */
__device__ float g_S  [(size_t)NH * NB * HD * HD];    /* per-block KV sums     */
__device__ float g_KV [(size_t)NH * NB * HD * HD];    /* pre-block KV states   */
__device__ float g_hid[(size_t)NTOK * HID];           /* attention output      */
__device__ float g_tmp[(size_t)NTOK * HID];           /* gate * norm(hidden)   */
__device__ float g_rstd[NTOK];

/* ------------------------------ f32x2 helpers ------------------------------ */
__device__ __forceinline__ float2 u2f2(unsigned long long u) {
    float2 r; asm("mov.b64 {%0,%1}, %2;" : "=f"(r.x), "=f"(r.y) : "l"(u)); return r;
}
__device__ __forceinline__ void ffma2(unsigned long long &c,
                                      unsigned long long a, unsigned long long b) {
    asm("fma.rn.f32x2 %0, %1, %2, %0;" : "+l"(c) : "l"(a), "l"(b));
}

__device__ __forceinline__ float head_slope(int h) {
    /* SLOPE[h] = 2^(-0.25*(h+1)) * (1 + 1e-5)  for H=32, LAYER_IDX=0 */
    return exp2f(-0.25f * (float)(h + 1)) * 1.00001f;
}

/* ------------------------------ main SGEMM --------------------------------- */
/* C[m,n] = epi( sum_k A[m,k] * B[n,k] )   (A: MxK row-major, B: NxK row-major)
   EPI: 0 = none, 1 = silu, 2 = sigmoid(x)*auxH[m,n]*auxR[m]*auxW[n]           */
template<int EPI>
__global__ void __launch_bounds__(256, 2) sgemm_kernel(
    const float* __restrict__ A, const float* __restrict__ B, float* __restrict__ C,
    int M, int N, int K,
    const float* __restrict__ auxH, const float* __restrict__ auxR,
    const float* __restrict__ auxW)
{
    __shared__ float As2[8][256];   /* A tile, every value duplicated (pairs) */
    __shared__ float Bs [8][128];

    const int tid = threadIdx.x;
    const int bm  = blockIdx.y << 7;
    const int bn  = blockIdx.x << 7;
    const int lr  = tid >> 1;          /* 0..127 row in tile       */
    const int lc  = (tid & 1) << 2;    /* 0 or 4  k offset          */
    const int tx  = tid & 15;          /* col group (8 cols each)   */
    const int ty  = tid >> 4;          /* row group (8 rows each)   */

    const float* Ap = A + (size_t)(bm + lr) * K + lc;
    const float* Bp = B + (size_t)(bn + lr) * K + lc;

    unsigned long long acc[8][4];
#pragma unroll
    for (int i = 0; i < 8; i++)
#pragma unroll
        for (int j = 0; j < 4; j++) acc[i][j] = 0ULL;

    float4 av = *(const float4*)Ap;
    float4 bv = *(const float4*)Bp;

    for (int k0 = 0; k0 < K; k0 += 8) {
        __syncthreads();
        As2[lc+0][2*lr] = av.x; As2[lc+0][2*lr+1] = av.x;
        As2[lc+1][2*lr] = av.y; As2[lc+1][2*lr+1] = av.y;
        As2[lc+2][2*lr] = av.z; As2[lc+2][2*lr+1] = av.z;
        As2[lc+3][2*lr] = av.w; As2[lc+3][2*lr+1] = av.w;
        Bs[lc+0][lr] = bv.x; Bs[lc+1][lr] = bv.y;
        Bs[lc+2][lr] = bv.z; Bs[lc+3][lr] = bv.w;
        __syncthreads();
        if (k0 + 8 < K) {                 /* prefetch next tile into regs */
            av = *(const float4*)(Ap + k0 + 8);
            bv = *(const float4*)(Bp + k0 + 8);
        }
#pragma unroll
        for (int kk = 0; kk < 8; kk++) {
            unsigned long long b2[4];
#pragma unroll
            for (int j = 0; j < 4; j++)
                b2[j] = *(const unsigned long long*)&Bs[kk][tx*8 + j*2];
#pragma unroll
            for (int i = 0; i < 8; i++) {
                unsigned long long a2 =
                    *(const unsigned long long*)&As2[kk][(ty*8 + i)*2];
#pragma unroll
                for (int j = 0; j < 4; j++) ffma2(acc[i][j], a2, b2[j]);
            }
        }
    }

#pragma unroll
    for (int i = 0; i < 8; i++) {
        const int m = bm + ty*8 + i;
        float vals[8];
#pragma unroll
        for (int j = 0; j < 4; j++) {
            float2 v = u2f2(acc[i][j]);
            vals[2*j] = v.x; vals[2*j+1] = v.y;
        }
        float outv[8];
#pragma unroll
        for (int jj = 0; jj < 8; jj++) {
            const int n = bn + tx*8 + jj;
            float x = vals[jj];
            float r;
            if (EPI == 0) {
                r = x;
            } else if (EPI == 1) {
                r = x / (1.f + expf(-x));                       /* silu */
            } else {
                float g = 1.f / (1.f + expf(-x));               /* sigmoid gate */
                r = g * auxH[(size_t)m * N + n] * auxR[m] * auxW[n];
            }
            outv[jj] = r;
        }
        float4* cp = (float4*)(C + (size_t)m * N + bn + tx*8);
        cp[0] = make_float4(outv[0], outv[1], outv[2], outv[3]);
        cp[1] = make_float4(outv[4], outv[5], outv[6], outv[7]);
    }
}

/* ----------------- attention A: per-block KV outer-product sums ------------ */
/* S[h,blk,d,e] = sum_n k[h, blk*256+n, d] * exp(-s*(255-n)) * v[h, blk*256+n, e] */
__global__ void __launch_bounds__(256) attn_kvsum_kernel(
    const float* __restrict__ qkv, float* __restrict__ S)
{
    const int blk = blockIdx.x, h = blockIdx.y;
    __shared__ float Ks[64][65];
    __shared__ float Vs[64][65];
    __shared__ float tab[257];

    const int tid = threadIdx.x;
    const float slope = head_slope(h);
    for (int i = tid; i < 257; i += 256) tab[i] = expf(-slope * (float)i);

    const int tx = tid & 15, ty = tid >> 4;
    float acc[4][4];
#pragma unroll
    for (int i = 0; i < 4; i++)
#pragma unroll
        for (int j = 0; j < 4; j++) acc[i][j] = 0.f;

    for (int nc = 0; nc < 4; nc++) {
        __syncthreads();
        for (int idx = tid; idx < 1024; idx += 256) {
            int n  = idx >> 4;
            int d4 = (idx & 15) << 2;
            int ng = nc*64 + n;
            const float* base = qkv + (size_t)(blk*256 + ng) * QKVW + h*192;
            float4 k4 = *(const float4*)(base + 64 + d4);
            float  kd = tab[255 - ng];
            Ks[n][d4+0] = k4.x*kd; Ks[n][d4+1] = k4.y*kd;
            Ks[n][d4+2] = k4.z*kd; Ks[n][d4+3] = k4.w*kd;
            float4 v4 = *(const float4*)(base + 128 + d4);
            Vs[n][d4+0] = v4.x; Vs[n][d4+1] = v4.y;
            Vs[n][d4+2] = v4.z; Vs[n][d4+3] = v4.w;
        }
        __syncthreads();
#pragma unroll 8
        for (int n = 0; n < 64; n++) {
            float a[4], b[4];
#pragma unroll
            for (int i = 0; i < 4; i++) a[i] = Ks[n][ty*4 + i];
#pragma unroll
            for (int j = 0; j < 4; j++) b[j] = Vs[n][tx*4 + j];
#pragma unroll
            for (int i = 0; i < 4; i++)
#pragma unroll
                for (int j = 0; j < 4; j++) acc[i][j] += a[i]*b[j];
        }
    }
    float* sp = S + ((size_t)h*NB + blk)*4096;
#pragma unroll
    for (int i = 0; i < 4; i++)
        *(float4*)(sp + (ty*4 + i)*64 + tx*4) =
            make_float4(acc[i][0], acc[i][1], acc[i][2], acc[i][3]);
}

/* ---------------- attention B: scan of KV states across blocks ------------- */
__global__ void __launch_bounds__(256) attn_scan_kernel(
    const float* __restrict__ S, const float* __restrict__ kv0,
    float* __restrict__ KV)
{
    const int h = blockIdx.x, tid = threadIdx.x;
    const float bd = expf(-head_slope(h) * 256.f);
    float kv[16];
#pragma unroll
    for (int i = 0; i < 16; i++) kv[i] = kv0[(size_t)h*4096 + tid + i*256];
    for (int j = 0; j < NB; j++) {
        size_t base = ((size_t)h*NB + j)*4096;
#pragma unroll
        for (int i = 0; i < 16; i++) {
            KV[base + tid + i*256] = kv[i];
            kv[i] = bd*kv[i] + S[base + tid + i*256];
        }
    }
}

/* -------- attention C: per (head, block) output tile (inter + intra) ------- */
#define ATTN_SMEM_FLOATS (288 + 2*256*65 + 3*64*65)
#define ATTN_SMEM_BYTES  (ATTN_SMEM_FLOATS * 4)

__global__ void __launch_bounds__(256) attn_out_kernel(
    const float* __restrict__ qkv, const float* __restrict__ KV,
    float* __restrict__ hid)
{
    extern __shared__ float sm[];
    float* tab = sm;                       /* 257 (+pad)            */
    float* Qs  = sm + 288;                 /* 256 x 65  [m][d]      */
    float* Ps  = Qs + 256*65;              /* 256 x 65  [m][n_loc]  */
    float* Ks  = Ps + 256*65;              /* 64  x 65  [d][n]  K^T */
    float* Vs  = Ks + 64*65;               /* 64  x 65  [n][e]      */
    float* KVs = Vs + 64*65;               /* 64  x 65  [d][e]      */

    const int blk = blockIdx.x, h = blockIdx.y;
    const int tid = threadIdx.x;
    const float slope = head_slope(h);
    for (int i = tid; i < 257; i += 256) tab[i] = expf(-slope * (float)i);

    for (int idx = tid; idx < 4096; idx += 256) {        /* load Q 256x64 */
        int m = idx >> 4, d4 = (idx & 15) << 2;
        float4 q4 = *(const float4*)(qkv + (size_t)(blk*256 + m)*QKVW + h*192 + d4);
        float* qp = Qs + m*65 + d4;
        qp[0] = q4.x; qp[1] = q4.y; qp[2] = q4.z; qp[3] = q4.w;
    }
    for (int idx = tid; idx < 1024; idx += 256) {        /* load KV state */
        int d = idx >> 4, e4 = (idx & 15) << 2;
        float4 v4 = *(const float4*)(KV + ((size_t)h*NB + blk)*4096 + d*64 + e4);
        float* kp = KVs + d*65 + e4;
        kp[0] = v4.x; kp[1] = v4.y; kp[2] = v4.z; kp[3] = v4.w;
    }
    __syncthreads();

    const int tx = tid & 7;        /* 8 col groups  (8 cols each) */
    const int ty = tid >> 3;       /* 32 row groups (8 rows each) */
    const int m0 = ty * 8;

    float acc[8][8];
#pragma unroll
    for (int i = 0; i < 8; i++)
#pragma unroll
        for (int j = 0; j < 8; j++) acc[i][j] = 0.f;

    /* inter: (Q .* q_decay) @ KV */
#pragma unroll 4
    for (int d = 0; d < 64; d++) {
        float a[8], b[8];
#pragma unroll
        for (int i = 0; i < 8; i++) a[i] = Qs[(m0 + i)*65 + d];
#pragma unroll
        for (int j = 0; j < 8; j++) b[j] = KVs[d*65 + tx*8 + j];
#pragma unroll
        for (int i = 0; i < 8; i++)
#pragma unroll
            for (int j = 0; j < 8; j++) acc[i][j] += a[i]*b[j];
    }
#pragma unroll
    for (int i = 0; i < 8; i++) {
        float qd = tab[m0 + i + 1];
#pragma unroll
        for (int j = 0; j < 8; j++) acc[i][j] *= qd;
    }

    for (int nc = 0; nc < 4; nc++) {
        __syncthreads();
        for (int idx = tid; idx < 1024; idx += 256) {    /* load K^T, V chunk */
            int n = idx >> 4, d4 = (idx & 15) << 2;
            const float* base = qkv + (size_t)(blk*256 + nc*64 + n)*QKVW + h*192;
            float4 k4 = *(const float4*)(base + 64 + d4);
            Ks[(d4+0)*65 + n] = k4.x; Ks[(d4+1)*65 + n] = k4.y;
            Ks[(d4+2)*65 + n] = k4.z; Ks[(d4+3)*65 + n] = k4.w;
            float4 v4 = *(const float4*)(base + 128 + d4);
            float* vp = Vs + n*65 + d4;
            vp[0] = v4.x; vp[1] = v4.y; vp[2] = v4.z; vp[3] = v4.w;
        }
        __syncthreads();

        if (m0 + 7 >= nc*64) {               /* warp-uniform triangular skip */
            float p[8][8];
#pragma unroll
            for (int i = 0; i < 8; i++)
#pragma unroll
                for (int j = 0; j < 8; j++) p[i][j] = 0.f;
#pragma unroll 4
            for (int d = 0; d < 64; d++) {
                float a[8], b[8];
#pragma unroll
                for (int i = 0; i < 8; i++) a[i] = Qs[(m0 + i)*65 + d];
#pragma unroll
                for (int j = 0; j < 8; j++) b[j] = Ks[d*65 + tx*8 + j];
#pragma unroll
                for (int i = 0; i < 8; i++)
#pragma unroll
                    for (int j = 0; j < 8; j++) p[i][j] += a[i]*b[j];
            }
            /* decayed causal mask, P rows are private to this warp */
#pragma unroll
            for (int i = 0; i < 8; i++) {
                int mm = m0 + i;
#pragma unroll
                for (int j = 0; j < 8; j++) {
                    int nn = nc*64 + tx*8 + j;
                    int delta = mm - nn;
                    Ps[mm*65 + tx*8 + j] = (delta >= 0) ? p[i][j]*tab[delta] : 0.f;
                }
            }
            __syncwarp();
#pragma unroll 4
            for (int n = 0; n < 64; n++) {
                float a[8], b[8];
#pragma unroll
                for (int i = 0; i < 8; i++) a[i] = Ps[(m0 + i)*65 + n];
#pragma unroll
                for (int j = 0; j < 8; j++) b[j] = Vs[n*65 + tx*8 + j];
#pragma unroll
                for (int i = 0; i < 8; i++)
#pragma unroll
                    for (int j = 0; j < 8; j++) acc[i][j] += a[i]*b[j];
            }
        }
    }

    float* op = hid + (size_t)(blk*256) * HID + h*64;
#pragma unroll
    for (int i = 0; i < 8; i++) {
        float4* dst = (float4*)(op + (size_t)(m0 + i)*HID + tx*8);
        dst[0] = make_float4(acc[i][0], acc[i][1], acc[i][2], acc[i][3]);
        dst[1] = make_float4(acc[i][4], acc[i][5], acc[i][6], acc[i][7]);
    }
}

/* --------------------------- rmsnorm rstd vector --------------------------- */
__global__ void __launch_bounds__(256) rms_kernel(
    const float* __restrict__ hid, float* __restrict__ rstd)
{
    const int row = blockIdx.x, tid = threadIdx.x;
    const float* p = hid + (size_t)row * HID;
    float s = 0.f;
    {
        int i = tid * 8;
        float4 a = *(const float4*)(p + i);
        float4 b = *(const float4*)(p + i + 4);
        s = a.x*a.x + a.y*a.y + a.z*a.z + a.w*a.w
          + b.x*b.x + b.y*b.y + b.z*b.z + b.w*b.w;
    }
#pragma unroll
    for (int off = 16; off; off >>= 1) s += __shfl_xor_sync(~0u, s, off);
    __shared__ float red[8];
    if ((tid & 31) == 0) red[tid >> 5] = s;
    __syncthreads();
    if (tid < 8) {
        float v = red[tid];
#pragma unroll
        for (int off = 4; off; off >>= 1) v += __shfl_xor_sync(0xffu, v, off);
        if (tid == 0) rstd[row] = rsqrtf(v * (1.f / HID) + 1e-5f);
    }
}

/* --------------------------------- launch ---------------------------------- */
extern "C" void kernel_launch(void* const* d_in, const int* in_sizes, int n_in,
                              void* d_out, int out_size)
{
    (void)in_sizes; (void)n_in; (void)out_size;
    const float* hs   = (const float*)d_in[0];   /* hidden_states 8192x2048 */
    const float* kv0  = (const float*)d_in[1];   /* kv_cache 32x64x64       */
    const float* Wqkv = (const float*)d_in[2];   /* 6144x2048               */
    const float* Wg   = (const float*)d_in[3];   /* 2048x2048               */
    const float* Wo   = (const float*)d_in[4];   /* 2048x2048               */
    const float* nw   = (const float*)d_in[5];   /* 2048                    */
    float* out = (float*)d_out;

    float *qkv, *S, *KV, *hid, *tmp, *rstd;
    cudaGetSymbolAddress((void**)&qkv,  g_qkv);
    cudaGetSymbolAddress((void**)&S,    g_S);
    cudaGetSymbolAddress((void**)&KV,   g_KV);
    cudaGetSymbolAddress((void**)&hid,  g_hid);
    cudaGetSymbolAddress((void**)&tmp,  g_tmp);
    cudaGetSymbolAddress((void**)&rstd, g_rstd);

    cudaFuncSetAttribute(attn_out_kernel,
                         cudaFuncAttributeMaxDynamicSharedMemorySize,
                         ATTN_SMEM_BYTES);

    /* 1. qkv = silu(hs @ Wqkv^T) */
    sgemm_kernel<1><<<dim3(48, 64), 256>>>(hs, Wqkv, qkv, NTOK, QKVW, HID,
                                           nullptr, nullptr, nullptr);
    /* 2-4. lightning attention */
    attn_kvsum_kernel<<<dim3(NB, NH), 256>>>(qkv, S);
    attn_scan_kernel<<<NH, 256>>>(S, kv0, KV);
    attn_out_kernel<<<dim3(NB, NH), 256, ATTN_SMEM_BYTES>>>(qkv, KV, hid);
    /* 5. rmsnorm scale vector */
    rms_kernel<<<NTOK, 256>>>(hid, rstd);
    /* 6. tmp = sigmoid(hs @ Wg^T) * hid * rstd * nw   (norm fused in epilogue) */
    sgemm_kernel<2><<<dim3(16, 64), 256>>>(hs, Wg, tmp, NTOK, HID, HID,
                                           hid, rstd, nw);
    /* 7. out = tmp @ Wo^T */
    sgemm_kernel<0><<<dim3(16, 64), 256>>>(tmp, Wo, out, NTOK, HID, HID,
                                           nullptr, nullptr, nullptr);
}

// round 3
// speedup vs baseline: 2.0751x; 2.0751x over previous
#include <cuda_runtime.h>
#include <cuda_bf16.h>
#include <math.h>
#include <stdint.h>

#define HID   2048
#define NTOK  8192
#define NH    32
#define HD    64
#define NB    32            /* 8192 / 256 */
#define QKVW  (3*HID)       /* 6144 */

/* ------------------- GEMM tiling (mma.sync bf16 split) --------------------- */
#define BM 128
#define BN 128
#define BK 32
#define ST_A_HI 0
#define ST_A_LO 8192
#define ST_B_HI 16384
#define ST_B_LO 24576
#define STAGE_BYTES 32768
#define GEMM_SMEM (2*STAGE_BYTES)     /* 64 KB */

/* ------------------------- scratch (device globals) ------------------------ */
__device__ float g_qkv[(size_t)NTOK * QKVW];
__device__ float g_S  [(size_t)NH * NB * HD * HD];
__device__ float g_KV [(size_t)NH * NB * HD * HD];
__device__ float g_hid[(size_t)NTOK * HID];
__device__ float g_rstd[NTOK];
__device__ __nv_bfloat16 g_hs_hi  [(size_t)NTOK * HID];
__device__ __nv_bfloat16 g_hs_lo  [(size_t)NTOK * HID];
__device__ __nv_bfloat16 g_wqkv_hi[(size_t)QKVW * HID];
__device__ __nv_bfloat16 g_wqkv_lo[(size_t)QKVW * HID];
__device__ __nv_bfloat16 g_wg_hi  [(size_t)HID * HID];
__device__ __nv_bfloat16 g_wg_lo  [(size_t)HID * HID];
__device__ __nv_bfloat16 g_wo_hi  [(size_t)HID * HID];
__device__ __nv_bfloat16 g_wo_lo  [(size_t)HID * HID];
__device__ __nv_bfloat16 g_tmp_hi [(size_t)NTOK * HID];
__device__ __nv_bfloat16 g_tmp_lo [(size_t)NTOK * HID];

/* ------------------------------ PTX helpers -------------------------------- */
__device__ __forceinline__ uint32_t smem_u32(const void* p) {
    uint32_t a;
    asm("{ .reg .u64 t; cvta.to.shared.u64 t, %1; cvt.u32.u64 %0, t; }"
        : "=r"(a) : "l"(p));
    return a;
}
__device__ __forceinline__ void cp16(uint32_t dst, const void* src) {
    asm volatile("cp.async.cg.shared.global [%0], [%1], 16;"
                 :: "r"(dst), "l"(src));
}
#define CP_COMMIT()  asm volatile("cp.async.commit_group;" ::: "memory")
#define CP_WAIT(n)   asm volatile("cp.async.wait_group %0;" :: "n"(n) : "memory")

__device__ __forceinline__ void ldsm4(uint32_t* r, uint32_t addr) {
    asm volatile("ldmatrix.sync.aligned.m8n8.x4.shared.b16 {%0,%1,%2,%3}, [%4];"
                 : "=r"(r[0]), "=r"(r[1]), "=r"(r[2]), "=r"(r[3]) : "r"(addr));
}
__device__ __forceinline__ void mma16816(float* d, const uint32_t* a,
                                         const uint32_t* b) {
    asm volatile(
        "mma.sync.aligned.m16n8k16.row.col.f32.bf16.bf16.f32 "
        "{%0,%1,%2,%3}, {%4,%5,%6,%7}, {%8,%9}, {%0,%1,%2,%3};"
        : "+f"(d[0]), "+f"(d[1]), "+f"(d[2]), "+f"(d[3])
        : "r"(a[0]), "r"(a[1]), "r"(a[2]), "r"(a[3]), "r"(b[0]), "r"(b[1]));
}

__device__ __forceinline__ float head_slope(int h) {
    return exp2f(-0.25f * (float)(h + 1)) * 1.00001f;
}

/* tile-contiguous smem layout: tile(kch, tr) at (kch*16 + tr)*128 bytes,
   within-tile row slot = (row&7) ^ kch (both loads & stores use it).       */
__device__ __forceinline__ uint32_t sm_off(int row, int kch) {
    return ((uint32_t)(kch << 4) + (uint32_t)(row >> 3)) * 128u
         + (uint32_t)(((row & 7) ^ kch) << 4);
}

/* ------------------------ mma.sync split-bf16 GEMM ------------------------- */
/* C[m,n] = epi( sum_k A[m,k]*B[n,k] ), A=[M,K], B=[N,K] bf16 hi/lo pairs.
   EPI 0: C fp32.  EPI 1: silu -> C fp32.
   EPI 2: sigmoid(x)*auxH[m,n]*auxR[m]*auxW[n] -> split into Chi/Clo bf16.   */
template<int EPI>
__global__ void __launch_bounds__(256, 2) mma_gemm_kernel(
    const __nv_bfloat16* __restrict__ Ahi, const __nv_bfloat16* __restrict__ Alo,
    const __nv_bfloat16* __restrict__ Bhi, const __nv_bfloat16* __restrict__ Blo,
    int K, int ldC,
    float* __restrict__ C,
    __nv_bfloat16* __restrict__ Chi, __nv_bfloat16* __restrict__ Clo,
    const float* __restrict__ auxH, const float* __restrict__ auxR,
    const float* __restrict__ auxW)
{
    extern __shared__ char smraw[];
    const uint32_t smu = smem_u32(smraw);
    const int tid  = threadIdx.x;
    const int lane = tid & 31;
    const int wid  = tid >> 5;
    const int m0   = blockIdx.y * BM;
    const int n0   = blockIdx.x * BN;
    const int wm   = (wid >> 2) * 64;      /* 2 warp rows of 64 */
    const int wn   = (wid & 3)  * 32;      /* 4 warp cols of 32 */

    const int r0 = tid >> 2;               /* 0..63 */
    const int kq = tid & 3;                /* 16B chunk within 32-k row */

    float acc[4][4][4];
#pragma unroll
    for (int i = 0; i < 4; i++)
#pragma unroll
        for (int j = 0; j < 4; j++)
#pragma unroll
            for (int v = 0; v < 4; v++) acc[i][j][v] = 0.f;

    const int nch = K / BK;

    /* issue one 32-k chunk into stage s */
    auto issue = [&](int c, int s) {
        const int kc = c * BK;
        const uint32_t sb = smu + (uint32_t)s * STAGE_BYTES;
#pragma unroll
        for (int i = 0; i < 2; i++) {
            const int r = r0 + 64 * i;
            const uint32_t wo = sm_off(r, kq);
            const size_t ga = (size_t)(m0 + r) * K + kc + kq * 8;
            const size_t gb = (size_t)(n0 + r) * K + kc + kq * 8;
            cp16(sb + ST_A_HI + wo, Ahi + ga);
            cp16(sb + ST_A_LO + wo, Alo + ga);
            cp16(sb + ST_B_HI + wo, Bhi + gb);
            cp16(sb + ST_B_LO + wo, Blo + gb);
        }
        CP_COMMIT();
    };

    issue(0, 0);
    if (nch > 1) issue(1, 1);

    for (int c = 0; c < nch; c++) {
        if (c + 1 < nch) { CP_WAIT(1); } else { CP_WAIT(0); }
        __syncthreads();

        const uint32_t sb = smu + (uint32_t)(c & 1) * STAGE_BYTES;
#pragma unroll
        for (int ks = 0; ks < 2; ks++) {
            uint32_t a[4][4], bh[4][2], bl[4][2];
            /* B fragments: 2 ldmatrix.x4 each for hi/lo (2 n-atoms per ldsm) */
#pragma unroll
            for (int half = 0; half < 2; half++) {
                const int n   = wn + 16*half + ((lane >> 4) << 3) + (lane & 7);
                const int kch = 2*ks + ((lane >> 3) & 1);
                const uint32_t off = sm_off(n, kch);
                uint32_t t4[4];
                ldsm4(t4, sb + ST_B_HI + off);
                bh[2*half][0] = t4[0]; bh[2*half][1] = t4[1];
                bh[2*half+1][0] = t4[2]; bh[2*half+1][1] = t4[3];
                ldsm4(t4, sb + ST_B_LO + off);
                bl[2*half][0] = t4[0]; bl[2*half][1] = t4[1];
                bl[2*half+1][0] = t4[2]; bl[2*half+1][1] = t4[3];
            }
            /* A hi fragments */
#pragma unroll
            for (int am = 0; am < 4; am++) {
                const int row = wm + 16*am + (lane & 15);
                const int kch = 2*ks + (lane >> 4);
                ldsm4(a[am], sb + ST_A_HI + sm_off(row, kch));
            }
#pragma unroll
            for (int am = 0; am < 4; am++)
#pragma unroll
                for (int bn = 0; bn < 4; bn++) {
                    mma16816(acc[am][bn], a[am], bh[bn]);
                    mma16816(acc[am][bn], a[am], bl[bn]);
                }
            /* A lo fragments (reuse regs) */
#pragma unroll
            for (int am = 0; am < 4; am++) {
                const int row = wm + 16*am + (lane & 15);
                const int kch = 2*ks + (lane >> 4);
                ldsm4(a[am], sb + ST_A_LO + sm_off(row, kch));
            }
#pragma unroll
            for (int am = 0; am < 4; am++)
#pragma unroll
                for (int bn = 0; bn < 4; bn++)
                    mma16816(acc[am][bn], a[am], bh[bn]);
        }
        __syncthreads();
        if (c + 2 < nch) issue(c + 2, c & 1);
    }

    /* --------------------------- epilogue ---------------------------------- */
    const int g  = lane >> 2;
    const int t2 = (lane & 3) * 2;
#pragma unroll
    for (int am = 0; am < 4; am++)
#pragma unroll
        for (int bn = 0; bn < 4; bn++) {
            const int n = n0 + wn + 8*bn + t2;
#pragma unroll
            for (int half = 0; half < 2; half++) {
                const int m = m0 + wm + 16*am + g + 8*half;
                const float x0 = acc[am][bn][2*half + 0];
                const float x1 = acc[am][bn][2*half + 1];
                const size_t off = (size_t)m * ldC + n;
                if (EPI == 0) {
                    *(float2*)(C + off) = make_float2(x0, x1);
                } else if (EPI == 1) {
                    *(float2*)(C + off) = make_float2(
                        x0 / (1.f + expf(-x0)), x1 / (1.f + expf(-x1)));
                } else {
                    float2 hv = *(const float2*)(auxH + off);
                    float2 wv = *(const float2*)(auxW + n);
                    float rr = auxR[m];
                    float r0v = hv.x * rr * wv.x / (1.f + expf(-x0));
                    float r1v = hv.y * rr * wv.y / (1.f + expf(-x1));
                    __nv_bfloat16 h0 = __float2bfloat16(r0v);
                    __nv_bfloat16 h1 = __float2bfloat16(r1v);
                    __nv_bfloat162 H, L;
                    H.x = h0; H.y = h1;
                    L.x = __float2bfloat16(r0v - __bfloat162float(h0));
                    L.y = __float2bfloat16(r1v - __bfloat162float(h1));
                    *(__nv_bfloat162*)(Chi + off) = H;
                    *(__nv_bfloat162*)(Clo + off) = L;
                }
            }
        }
}

/* --------------------------- fp32 -> bf16 hi/lo split ----------------------- */
__global__ void __launch_bounds__(256) split_kernel(
    const float4* __restrict__ src, __nv_bfloat162* __restrict__ hi,
    __nv_bfloat162* __restrict__ lo, int n4)
{
    int i = blockIdx.x * blockDim.x + threadIdx.x;
    if (i >= n4) return;
    float4 v = src[i];
    __nv_bfloat16 h0 = __float2bfloat16(v.x), h1 = __float2bfloat16(v.y);
    __nv_bfloat16 h2 = __float2bfloat16(v.z), h3 = __float2bfloat16(v.w);
    __nv_bfloat162 H0, H1, L0, L1;
    H0.x = h0; H0.y = h1; H1.x = h2; H1.y = h3;
    L0.x = __float2bfloat16(v.x - __bfloat162float(h0));
    L0.y = __float2bfloat16(v.y - __bfloat162float(h1));
    L1.x = __float2bfloat16(v.z - __bfloat162float(h2));
    L1.y = __float2bfloat16(v.w - __bfloat162float(h3));
    hi[2*i] = H0; hi[2*i+1] = H1;
    lo[2*i] = L0; lo[2*i+1] = L1;
}

/* ----------------- attention A: per-block KV outer-product sums ------------ */
__global__ void __launch_bounds__(256) attn_kvsum_kernel(
    const float* __restrict__ qkv, float* __restrict__ S)
{
    const int blk = blockIdx.x, h = blockIdx.y;
    __shared__ float Ks[64][65];
    __shared__ float Vs[64][65];
    __shared__ float tab[257];

    const int tid = threadIdx.x;
    const float slope = head_slope(h);
    for (int i = tid; i < 257; i += 256) tab[i] = expf(-slope * (float)i);

    const int tx = tid & 15, ty = tid >> 4;
    float acc[4][4];
#pragma unroll
    for (int i = 0; i < 4; i++)
#pragma unroll
        for (int j = 0; j < 4; j++) acc[i][j] = 0.f;

    for (int nc = 0; nc < 4; nc++) {
        __syncthreads();
        for (int idx = tid; idx < 1024; idx += 256) {
            int n  = idx >> 4;
            int d4 = (idx & 15) << 2;
            int ng = nc*64 + n;
            const float* base = qkv + (size_t)(blk*256 + ng) * QKVW + h*192;
            float4 k4 = *(const float4*)(base + 64 + d4);
            float  kd = tab[255 - ng];
            Ks[n][d4+0] = k4.x*kd; Ks[n][d4+1] = k4.y*kd;
            Ks[n][d4+2] = k4.z*kd; Ks[n][d4+3] = k4.w*kd;
            float4 v4 = *(const float4*)(base + 128 + d4);
            Vs[n][d4+0] = v4.x; Vs[n][d4+1] = v4.y;
            Vs[n][d4+2] = v4.z; Vs[n][d4+3] = v4.w;
        }
        __syncthreads();
#pragma unroll 8
        for (int n = 0; n < 64; n++) {
            float a[4], b[4];
#pragma unroll
            for (int i = 0; i < 4; i++) a[i] = Ks[n][ty*4 + i];
#pragma unroll
            for (int j = 0; j < 4; j++) b[j] = Vs[n][tx*4 + j];
#pragma unroll
            for (int i = 0; i < 4; i++)
#pragma unroll
                for (int j = 0; j < 4; j++) acc[i][j] += a[i]*b[j];
        }
    }
    float* sp = S + ((size_t)h*NB + blk)*4096;
#pragma unroll
    for (int i = 0; i < 4; i++)
        *(float4*)(sp + (ty*4 + i)*64 + tx*4) =
            make_float4(acc[i][0], acc[i][1], acc[i][2], acc[i][3]);
}

/* ---------------- attention B: scan of KV states across blocks ------------- */
__global__ void __launch_bounds__(256) attn_scan_kernel(
    const float* __restrict__ S, const float* __restrict__ kv0,
    float* __restrict__ KV)
{
    const int h = blockIdx.x, tid = threadIdx.x;
    const float bd = expf(-head_slope(h) * 256.f);
    float kv[16];
#pragma unroll
    for (int i = 0; i < 16; i++) kv[i] = kv0[(size_t)h*4096 + tid + i*256];
    for (int j = 0; j < NB; j++) {
        size_t base = ((size_t)h*NB + j)*4096;
#pragma unroll
        for (int i = 0; i < 16; i++) {
            KV[base + tid + i*256] = kv[i];
            kv[i] = bd*kv[i] + S[base + tid + i*256];
        }
    }
}

/* -------- attention C: per (head, block) output tile (inter + intra) ------- */
#define ATTN_SMEM_FLOATS (288 + 2*256*65 + 3*64*65)
#define ATTN_SMEM_BYTES  (ATTN_SMEM_FLOATS * 4)

__global__ void __launch_bounds__(256) attn_out_kernel(
    const float* __restrict__ qkv, const float* __restrict__ KV,
    float* __restrict__ hid)
{
    extern __shared__ float sm[];
    float* tab = sm;
    float* Qs  = sm + 288;
    float* Ps  = Qs + 256*65;
    float* Ks  = Ps + 256*65;
    float* Vs  = Ks + 64*65;
    float* KVs = Vs + 64*65;

    const int blk = blockIdx.x, h = blockIdx.y;
    const int tid = threadIdx.x;
    const float slope = head_slope(h);
    for (int i = tid; i < 257; i += 256) tab[i] = expf(-slope * (float)i);

    for (int idx = tid; idx < 4096; idx += 256) {
        int m = idx >> 4, d4 = (idx & 15) << 2;
        float4 q4 = *(const float4*)(qkv + (size_t)(blk*256 + m)*QKVW + h*192 + d4);
        float* qp = Qs + m*65 + d4;
        qp[0] = q4.x; qp[1] = q4.y; qp[2] = q4.z; qp[3] = q4.w;
    }
    for (int idx = tid; idx < 1024; idx += 256) {
        int d = idx >> 4, e4 = (idx & 15) << 2;
        float4 v4 = *(const float4*)(KV + ((size_t)h*NB + blk)*4096 + d*64 + e4);
        float* kp = KVs + d*65 + e4;
        kp[0] = v4.x; kp[1] = v4.y; kp[2] = v4.z; kp[3] = v4.w;
    }
    __syncthreads();

    const int tx = tid & 7;
    const int ty = tid >> 3;
    const int m0 = ty * 8;

    float acc[8][8];
#pragma unroll
    for (int i = 0; i < 8; i++)
#pragma unroll
        for (int j = 0; j < 8; j++) acc[i][j] = 0.f;

#pragma unroll 4
    for (int d = 0; d < 64; d++) {
        float a[8], b[8];
#pragma unroll
        for (int i = 0; i < 8; i++) a[i] = Qs[(m0 + i)*65 + d];
#pragma unroll
        for (int j = 0; j < 8; j++) b[j] = KVs[d*65 + tx*8 + j];
#pragma unroll
        for (int i = 0; i < 8; i++)
#pragma unroll
            for (int j = 0; j < 8; j++) acc[i][j] += a[i]*b[j];
    }
#pragma unroll
    for (int i = 0; i < 8; i++) {
        float qd = tab[m0 + i + 1];
#pragma unroll
        for (int j = 0; j < 8; j++) acc[i][j] *= qd;
    }

    for (int nc = 0; nc < 4; nc++) {
        __syncthreads();
        for (int idx = tid; idx < 1024; idx += 256) {
            int n = idx >> 4, d4 = (idx & 15) << 2;
            const float* base = qkv + (size_t)(blk*256 + nc*64 + n)*QKVW + h*192;
            float4 k4 = *(const float4*)(base + 64 + d4);
            Ks[(d4+0)*65 + n] = k4.x; Ks[(d4+1)*65 + n] = k4.y;
            Ks[(d4+2)*65 + n] = k4.z; Ks[(d4+3)*65 + n] = k4.w;
            float4 v4 = *(const float4*)(base + 128 + d4);
            float* vp = Vs + n*65 + d4;
            vp[0] = v4.x; vp[1] = v4.y; vp[2] = v4.z; vp[3] = v4.w;
        }
        __syncthreads();

        if (m0 + 7 >= nc*64) {
            float p[8][8];
#pragma unroll
            for (int i = 0; i < 8; i++)
#pragma unroll
                for (int j = 0; j < 8; j++) p[i][j] = 0.f;
#pragma unroll 4
            for (int d = 0; d < 64; d++) {
                float a[8], b[8];
#pragma unroll
                for (int i = 0; i < 8; i++) a[i] = Qs[(m0 + i)*65 + d];
#pragma unroll
                for (int j = 0; j < 8; j++) b[j] = Ks[d*65 + tx*8 + j];
#pragma unroll
                for (int i = 0; i < 8; i++)
#pragma unroll
                    for (int j = 0; j < 8; j++) p[i][j] += a[i]*b[j];
            }
#pragma unroll
            for (int i = 0; i < 8; i++) {
                int mm = m0 + i;
#pragma unroll
                for (int j = 0; j < 8; j++) {
                    int nn = nc*64 + tx*8 + j;
                    int delta = mm - nn;
                    Ps[mm*65 + tx*8 + j] = (delta >= 0) ? p[i][j]*tab[delta] : 0.f;
                }
            }
            __syncwarp();
#pragma unroll 4
            for (int n = 0; n < 64; n++) {
                float a[8], b[8];
#pragma unroll
                for (int i = 0; i < 8; i++) a[i] = Ps[(m0 + i)*65 + n];
#pragma unroll
                for (int j = 0; j < 8; j++) b[j] = Vs[n*65 + tx*8 + j];
#pragma unroll
                for (int i = 0; i < 8; i++)
#pragma unroll
                    for (int j = 0; j < 8; j++) acc[i][j] += a[i]*b[j];
            }
        }
    }

    float* op = hid + (size_t)(blk*256) * HID + h*64;
#pragma unroll
    for (int i = 0; i < 8; i++) {
        float4* dst = (float4*)(op + (size_t)(m0 + i)*HID + tx*8);
        dst[0] = make_float4(acc[i][0], acc[i][1], acc[i][2], acc[i][3]);
        dst[1] = make_float4(acc[i][4], acc[i][5], acc[i][6], acc[i][7]);
    }
}

/* --------------------------- rmsnorm rstd vector --------------------------- */
__global__ void __launch_bounds__(256) rms_kernel(
    const float* __restrict__ hid, float* __restrict__ rstd)
{
    const int row = blockIdx.x, tid = threadIdx.x;
    const float* p = hid + (size_t)row * HID;
    float s = 0.f;
    {
        int i = tid * 8;
        float4 a = *(const float4*)(p + i);
        float4 b = *(const float4*)(p + i + 4);
        s = a.x*a.x + a.y*a.y + a.z*a.z + a.w*a.w
          + b.x*b.x + b.y*b.y + b.z*b.z + b.w*b.w;
    }
#pragma unroll
    for (int off = 16; off; off >>= 1) s += __shfl_xor_sync(~0u, s, off);
    __shared__ float red[8];
    if ((tid & 31) == 0) red[tid >> 5] = s;
    __syncthreads();
    if (tid < 8) {
        float v = red[tid];
#pragma unroll
        for (int off = 4; off; off >>= 1) v += __shfl_xor_sync(0xffu, v, off);
        if (tid == 0) rstd[row] = rsqrtf(v * (1.f / HID) + 1e-5f);
    }
}

/* --------------------------------- launch ---------------------------------- */
extern "C" void kernel_launch(void* const* d_in, const int* in_sizes, int n_in,
                              void* d_out, int out_size)
{
    (void)in_sizes; (void)n_in; (void)out_size;
    const float* hs   = (const float*)d_in[0];
    const float* kv0  = (const float*)d_in[1];
    const float* Wqkv = (const float*)d_in[2];
    const float* Wg   = (const float*)d_in[3];
    const float* Wo   = (const float*)d_in[4];
    const float* nw   = (const float*)d_in[5];
    float* out = (float*)d_out;

    float *qkv, *S, *KV, *hid, *rstd;
    __nv_bfloat16 *hs_hi, *hs_lo, *wq_hi, *wq_lo, *wg_hi, *wg_lo, *wo_hi, *wo_lo;
    __nv_bfloat16 *tmp_hi, *tmp_lo;
    cudaGetSymbolAddress((void**)&qkv,  g_qkv);
    cudaGetSymbolAddress((void**)&S,    g_S);
    cudaGetSymbolAddress((void**)&KV,   g_KV);
    cudaGetSymbolAddress((void**)&hid,  g_hid);
    cudaGetSymbolAddress((void**)&rstd, g_rstd);
    cudaGetSymbolAddress((void**)&hs_hi, g_hs_hi);
    cudaGetSymbolAddress((void**)&hs_lo, g_hs_lo);
    cudaGetSymbolAddress((void**)&wq_hi, g_wqkv_hi);
    cudaGetSymbolAddress((void**)&wq_lo, g_wqkv_lo);
    cudaGetSymbolAddress((void**)&wg_hi, g_wg_hi);
    cudaGetSymbolAddress((void**)&wg_lo, g_wg_lo);
    cudaGetSymbolAddress((void**)&wo_hi, g_wo_hi);
    cudaGetSymbolAddress((void**)&wo_lo, g_wo_lo);
    cudaGetSymbolAddress((void**)&tmp_hi, g_tmp_hi);
    cudaGetSymbolAddress((void**)&tmp_lo, g_tmp_lo);

    cudaFuncSetAttribute(attn_out_kernel,
                         cudaFuncAttributeMaxDynamicSharedMemorySize, ATTN_SMEM_BYTES);
    cudaFuncSetAttribute(mma_gemm_kernel<0>,
                         cudaFuncAttributeMaxDynamicSharedMemorySize, GEMM_SMEM);
    cudaFuncSetAttribute(mma_gemm_kernel<1>,
                         cudaFuncAttributeMaxDynamicSharedMemorySize, GEMM_SMEM);
    cudaFuncSetAttribute(mma_gemm_kernel<2>,
                         cudaFuncAttributeMaxDynamicSharedMemorySize, GEMM_SMEM);

    /* 0. bf16 hi/lo splits */
    split_kernel<<<(NTOK*HID/4 + 255)/256, 256>>>(
        (const float4*)hs, (__nv_bfloat162*)hs_hi, (__nv_bfloat162*)hs_lo, NTOK*HID/4);
    split_kernel<<<(QKVW*HID/4 + 255)/256, 256>>>(
        (const float4*)Wqkv, (__nv_bfloat162*)wq_hi, (__nv_bfloat162*)wq_lo, QKVW*HID/4);
    split_kernel<<<(HID*HID/4 + 255)/256, 256>>>(
        (const float4*)Wg, (__nv_bfloat162*)wg_hi, (__nv_bfloat162*)wg_lo, HID*HID/4);
    split_kernel<<<(HID*HID/4 + 255)/256, 256>>>(
        (const float4*)Wo, (__nv_bfloat162*)wo_hi, (__nv_bfloat162*)wo_lo, HID*HID/4);

    /* 1. qkv = silu(hs @ Wqkv^T) */
    mma_gemm_kernel<1><<<dim3(QKVW/BN, NTOK/BM), 256, GEMM_SMEM>>>(
        hs_hi, hs_lo, wq_hi, wq_lo, HID, QKVW, qkv,
        nullptr, nullptr, nullptr, nullptr, nullptr);

    /* 2-4. lightning attention */
    attn_kvsum_kernel<<<dim3(NB, NH), 256>>>(qkv, S);
    attn_scan_kernel<<<NH, 256>>>(S, kv0, KV);
    attn_out_kernel<<<dim3(NB, NH), 256, ATTN_SMEM_BYTES>>>(qkv, KV, hid);

    /* 5. rmsnorm scale vector */
    rms_kernel<<<NTOK, 256>>>(hid, rstd);

    /* 6. tmp = sigmoid(hs @ Wg^T) * hid * rstd * nw -> bf16 hi/lo */
    mma_gemm_kernel<2><<<dim3(HID/BN, NTOK/BM), 256, GEMM_SMEM>>>(
        hs_hi, hs_lo, wg_hi, wg_lo, HID, HID, nullptr,
        tmp_hi, tmp_lo, hid, rstd, nw);

    /* 7. out = tmp @ Wo^T */
    mma_gemm_kernel<0><<<dim3(HID/BN, NTOK/BM), 256, GEMM_SMEM>>>(
        tmp_hi, tmp_lo, wo_hi, wo_lo, HID, HID, out,
        nullptr, nullptr, nullptr, nullptr, nullptr);
}